// round 7
// baseline (speedup 1.0000x reference)
#include <cuda_runtime.h>
#include <cstdint>

// SpikeFP8MulToFP32:
//   A, B: [N, 8] float 0/1 bit-vectors of fp8 e4m3 (order S,E3..E0,M2,M1,M0)
//   out : [N, 32] float 0/1 bit-vector of fp32(A_val * B_val), MSB (sign) first.
//
// Pure HBM streaming (268 MB in, 537 MB out). Measured so far (kernel time):
//   R1 SMEM stage, 1 row/thr, grid 16384:   115.9us, DRAM 78.8%
//   R2 v8 (256-bit) ld/st:                  121.1us  (regression)
//   R3 persistent 888-block pipeline:       132.1us  (regression)
//   R6 shuffle stores, 1 row/thr:           117.6us  (neutral -> barrier not
//                                            the limiter)
// R7: single variable = per-thread MLP. 2 rows/thread, all 8 LDG.128 issued
// upfront (128B in flight per thread vs 64B), same coalescing shape, shuffle
// redistribution, float4 .cs stores. Targets DRAM queue depth.

#define THREADS 256
#define ROWS_PER_BLOCK (THREADS * 2)

static __device__ __forceinline__ uint32_t bit_of(float f) {
    // inputs are exactly 0.0f (0x00000000) or 1.0f (0x3F800000): test bit 23
    return (__float_as_uint(f) >> 23) & 1u;
}

static __device__ __forceinline__ float decode_e4m3(float4 lo, float4 hi) {
    // lo = {S, E3, E2, E1}, hi = {E0, M2, M1, M0}
    uint32_t s = bit_of(lo.x);
    uint32_t e = (bit_of(lo.y) << 3) | (bit_of(lo.z) << 2) |
                 (bit_of(lo.w) << 1) |  bit_of(hi.x);
    uint32_t m = (bit_of(hi.y) << 2) | (bit_of(hi.z) << 1) | bit_of(hi.w);
    // normal: (8+m)*2^(e-10); subnormal: m*2^-9
    uint32_t M = e ? (8u + m) : m;
    int      E = e ? ((int)e - 10) : -9;
    float mag = (float)(int)M * __int_as_float((E + 127) << 23);
    // OR sign in so zero products keep their sign bit (-0.0 matters to the
    // reference's fp32 bitcast)
    return __uint_as_float(__float_as_uint(mag) | (s << 31));
}

// warp-local store of 32 rows' product words held in register p (one row per
// lane, rows [warp_row0, warp_row0+32)), fully coalesced float4 .cs stores
static __device__ __forceinline__ void store_warp_span(uint32_t p, int lane,
                                                       float4* __restrict__ out4,
                                                       int warp_row0, int nrows) {
    float4* wout = out4 + (size_t)warp_row0 * 8;
    const int rows_left = nrows - warp_row0;
    if (rows_left <= 0) return;
    const int q_limit  = rows_left >= 32 ? 256 : rows_left * 8;
    const int g_shift  = 28 - ((lane & 7) << 2);
    const int src_base = lane >> 3;

#pragma unroll
    for (int k = 0; k < 8; k++) {
        uint32_t ps = __shfl_sync(0xffffffffu, p, k * 4 + src_base);
        int q = k * 32 + lane;
        if (q < q_limit) {
            uint32_t t = ps >> g_shift;
            float4 o;
            o.x = __uint_as_float(((t >> 3) & 1u) * 0x3F800000u);
            o.y = __uint_as_float(((t >> 2) & 1u) * 0x3F800000u);
            o.z = __uint_as_float(((t >> 1) & 1u) * 0x3F800000u);
            o.w = __uint_as_float(( t        & 1u) * 0x3F800000u);
            __stcs(&wout[q], o);
        }
    }
}

__global__ void __launch_bounds__(THREADS)
spike_fp8_mul_kernel(const float4* __restrict__ A4,
                     const float4* __restrict__ B4,
                     float4* __restrict__ out4,
                     int nrows) {
    const int tid  = threadIdx.x;
    const int lane = tid & 31;
    const int base = blockIdx.x * ROWS_PER_BLOCK;
    const int r0   = base + tid;
    const int r1   = base + THREADS + tid;

    // ---- issue ALL 8 independent LDG.128 before any decode (MLP_p1 = 8)
    float4 a00, a01, b00, b01, a10, a11, b10, b11;
    const bool v0 = r0 < nrows;
    const bool v1 = r1 < nrows;
    if (v0) {
        size_t k = 2 * (size_t)r0;
        a00 = __ldcs(&A4[k]); a01 = __ldcs(&A4[k + 1]);
        b00 = __ldcs(&B4[k]); b01 = __ldcs(&B4[k + 1]);
    }
    if (v1) {
        size_t k = 2 * (size_t)r1;
        a10 = __ldcs(&A4[k]); a11 = __ldcs(&A4[k + 1]);
        b10 = __ldcs(&B4[k]); b11 = __ldcs(&B4[k + 1]);
    }

    uint32_t p0 = 0, p1 = 0;
    if (v0) p0 = __float_as_uint(decode_e4m3(a00, a01) * decode_e4m3(b00, b01));
    if (v1) p1 = __float_as_uint(decode_e4m3(a10, a11) * decode_e4m3(b10, b11));

    // ---- stores: two coalesced 4KB warp spans (rows of p0, then rows of p1)
    const int warp_row0 = r0 & ~31;
    store_warp_span(p0, lane, out4, warp_row0, nrows);
    store_warp_span(p1, lane, out4, warp_row0 + THREADS, nrows);
}

extern "C" void kernel_launch(void* const* d_in, const int* in_sizes, int n_in,
                              void* d_out, int out_size) {
    const float4* A4 = (const float4*)d_in[0];
    const float4* B4 = (const float4*)d_in[1];
    float4* out4 = (float4*)d_out;

    int nrows  = in_sizes[0] / 8;
    int blocks = (nrows + ROWS_PER_BLOCK - 1) / ROWS_PER_BLOCK;
    spike_fp8_mul_kernel<<<blocks, THREADS>>>(A4, B4, out4, nrows);
}